// round 13
// baseline (speedup 1.0000x reference)
#include <cuda_runtime.h>
#include <math_constants.h>

// Fixed shapes per reference setup_inputs
#define BATCH   8
#define NPTS    8192
#define NQ      (2 * BATCH * NPTS)     // 131072
#define EPSF    1e-12f
#define SCALE   (1.0f / 131072.0f)

// Grid parameters (cell hash: x fastest, z slowest)
#define G       32
#define NCELLS  (G * G * G)            // 32768
#define GLO     (-4.0f)
#define H       0.25f
#define INVH    4.0f
#define NCLOUD  16

#define NBLK    1024
#define NTHR    128

// Row stride NCELLS+4 keeps every row 16B-aligned for int4 access.
#define CSTRIDE (NCELLS + 4)

// Scratch (no cudaMalloc allowed). Zero-init at load. g_hist re-zeroed by
// phase D each launch; g_barc staggered-reset (see grid_barrier usage).
__device__ float4 g_pts[NCLOUD][NPTS];
__device__ int    g_hist[NCLOUD][NCELLS];
__device__ int    g_cellstart[NCLOUD][CSTRIDE];
__device__ int    g_btot[NBLK];
__device__ volatile int g_barc[4];

__device__ __forceinline__ int cell_coord(float v) {
    int c = (int)((v - GLO) * INVH);
    return min(max(c, 0), G - 1);
}

// Software grid barrier. Safe: __launch_bounds__(128,8) => 8 blocks/SM
// co-resident capability, 1024 <= 8*148, so all blocks are resident.
__device__ __forceinline__ void grid_barrier(int id) {
    __syncthreads();
    if (threadIdx.x == 0) {
        __threadfence();
        atomicAdd((int*)&g_barc[id], 1);
        while (g_barc[id] < NBLK) __nanosleep(64);
    }
    __syncthreads();
}

// Dual-accumulator candidate scan: two independent fminf chains halve the
// accumulator-dependency critical path.
__device__ __forceinline__ void scan_pts(const float4* __restrict__ P,
                                         int j0, int j1,
                                         float ax, float ay, float az,
                                         float& lbA, float& lbB) {
    int j = j0;
    for (; j + 1 < j1; j += 2) {
        float4 p = P[j];
        float4 r = P[j + 1];
        float tA = fmaf(az, p.z, p.w);
        float tB = fmaf(az, r.z, r.w);
        tA = fmaf(ay, p.y, tA);
        tB = fmaf(ay, r.y, tB);
        tA = fmaf(ax, p.x, tA);
        tB = fmaf(ax, r.x, tB);
        lbA = fminf(lbA, tA);
        lbB = fminf(lbB, tB);
    }
    if (j < j1) {
        float4 p = P[j];
        float t = fmaf(az, p.z, p.w);
        t = fmaf(ay, p.y, t);
        t = fmaf(ax, p.x, t);
        lbA = fminf(lbA, t);
    }
}

__global__ void __launch_bounds__(NTHR, 8)
fused_kernel(const float* __restrict__ xyz1,
             const float* __restrict__ xyz2,
             float* __restrict__ out) {
    __shared__ int   s_i[32];
    __shared__ float s_f[4];

    const int tix  = threadIdx.x;
    const int lane = tix & 31;
    const int warp = tix >> 5;
    const int b    = blockIdx.x;
    const int lin  = b * NTHR + tix;

    // ================= A: histogram + rank (+ housekeeping) =================
    // g_barc[3] was left set by the PREVIOUS launch; every block only reaches
    // barrier 3 after barrier 0, which needs block 0's arrival, which happens
    // after this reset. First launch: zero-init.
    if (lin == 0) { out[0] = 0.0f; g_barc[3] = 0; }

    int   src    = lin >> 16;                 // 0 or 1
    int   within = lin & 0xFFFF;
    const float* pp = ((src == 0) ? xyz1 : xyz2) + (size_t)within * 3;
    float px = pp[0], py = pp[1], pz = pp[2];         // live until phase C
    int   pcloud = (src << 3) + (within >> 13);
    int   pcell  = (cell_coord(pz) * G + cell_coord(py)) * G + cell_coord(px);
    int   prank  = atomicAdd(&g_hist[pcloud][pcell], 1);  // rank within cell

    grid_barrier(0);

    // ================= B1: block-local sums over 512 cells =================
    const int cloud_b = b >> 6;                       // 64 blocks per cloud
    const int cbase   = ((b & 63) << 9) + (tix << 2); // 4 cells per thread
    int4 h = *(const int4*)&g_hist[cloud_b][cbase];
    int hs = h.x + h.y + h.z + h.w;

    int incl = hs;                                    // warp inclusive scan
#pragma unroll
    for (int o = 1; o < 32; o <<= 1) {
        int u = __shfl_up_sync(0xFFFFFFFFu, incl, o);
        if (lane >= o) incl += u;
    }
    if (lane == 31) s_i[warp] = incl;
    __syncthreads();
    int woff = 0;
#pragma unroll
    for (int w = 0; w < 4; w++) if (w < warp) woff += s_i[w];
    int ebase = woff + incl - hs;                     // block-exclusive base
    if (tix == 0) g_btot[b] = s_i[0] + s_i[1] + s_i[2] + s_i[3];

    grid_barrier(1);

    // ================= B2: cross-block offsets, write cellstart =====
    if (lin == 0) g_barc[0] = 0;          // all blocks passed barrier 0's spin
    {
        int nb = b & 63;
        int v = (tix < nb) ? g_btot[(cloud_b << 6) + tix] : 0;
#pragma unroll
        for (int o = 16; o > 0; o >>= 1)
            v += __shfl_down_sync(0xFFFFFFFFu, v, o);
        __syncthreads();
        if (lane == 0) s_i[warp] = v;
        __syncthreads();
        int off  = s_i[0] + s_i[1] + s_i[2] + s_i[3];
        int base = off + ebase;
        int4 cs;
        cs.x = base;
        cs.y = cs.x + h.x;
        cs.z = cs.y + h.y;
        cs.w = cs.z + h.z;
        *(int4*)&g_cellstart[cloud_b][cbase] = cs;
        if (nb == 0 && tix == 0) g_cellstart[cloud_b][NCELLS] = NPTS;
    }

    grid_barrier(2);

    // ================= C: rank-based scatter (no atomics) =================
    if (lin == 0) g_barc[1] = 0;
    {
        int slot = g_cellstart[pcloud][pcell] + prank;
        g_pts[pcloud][slot] =
            make_float4(px, py, pz, px * px + py * py + pz * pz);
    }

    grid_barrier(3);

    // ================= D: query + tail + reduce =================
    if (lin == 0) g_barc[2] = 0;
    ((int4*)g_hist)[lin] = make_int4(0, 0, 0, 0);   // ready for next launch

    // warp remap: spreads dense/sparse regions; warp stays 32 contiguous
    int wid  = lin >> 5;
    int nwid = (wid & 31) * 128 + (wid >> 5);       // bijection on [0,4096)
    int tid  = nwid * 32 + lane;

    int cloud_q = tid >> 13;
    int i       = tid & (NPTS - 1);
    int cand    = cloud_q ^ 8;

    float4 q = g_pts[cloud_q][i];
    float n2q = q.w;
    float ax = -2.0f * q.x, ay = -2.0f * q.y, az = -2.0f * q.z;
    int cx = cell_coord(q.x);
    int cy = cell_coord(q.y);
    int cz = cell_coord(q.z);

    const float4* __restrict__ P = g_pts[cand];
    const int*    __restrict__ S = g_cellstart[cand];

    // pass 1: 3x3x3, hoisted headers (18 independent LDGs)
    int x0 = max(cx - 1, 0);
    int x1 = min(cx + 1, G - 1);
    int j0a[9], j1a[9];
#pragma unroll
    for (int k = 0; k < 9; k++) {
        int dz = k / 3 - 1;
        int dy = k - (k / 3) * 3 - 1;
        int zc = cz + dz, yc = cy + dy;
        bool ok = ((unsigned)zc < G) && ((unsigned)yc < G);
        int row = (zc * G + yc) * G;
        j0a[k] = ok ? S[row + x0] : 0;
        j1a[k] = ok ? S[row + x1 + 1] : 0;
    }
    float bA = CUDART_INF_F, bB = CUDART_INF_F;
#pragma unroll
    for (int k = 0; k < 9; k++)
        scan_pts(P, j0a[k], j1a[k], ax, ay, az, bA, bB);
    float best = fminf(bA, bB);

    float d2 = n2q + best;
    float contrib = 0.0f;
    bool done = (d2 <= H * H);
    if (done) contrib = sqrtf(fmaxf(d2, EPSF));

    // pass 2 (per-thread, parallel across needy lanes): full 5x5x5 rescan
    if (!done) {
#pragma unroll 5
        for (int k = 0; k < 25; k++) {
            int dz = k / 5 - 2;
            int dy = k - (k / 5) * 5 - 2;
            int zc = cz + dz, yc = cy + dy;
            if ((unsigned)zc >= G || (unsigned)yc >= G) continue;
            int row = (zc * G + yc) * G;
            if (abs(dz) == 2 || abs(dy) == 2) {
                int jx0 = max(cx - 2, 0), jx1 = min(cx + 2, G - 1);
                scan_pts(P, S[row + jx0], S[row + jx1 + 1], ax, ay, az, bA, bB);
            } else {
                int xm = cx - 2;
                if (xm >= 0) scan_pts(P, S[row + xm], S[row + xm + 1],
                                      ax, ay, az, bA, bB);
                int xp = cx + 2;
                if (xp < G)  scan_pts(P, S[row + xp], S[row + xp + 1],
                                      ax, ay, az, bA, bB);
            }
        }
        best = fminf(bA, bB);
        d2 = n2q + best;
        done = (d2 <= 4.0f * H * H);          // chebyshev-2 bound = 0.5
        if (done) contrib = sqrtf(fmaxf(d2, EPSF));
    }

    // residual (~0.5%): warp-cooperative z-slab doubling (z slowest sort dim)
    unsigned needy = __ballot_sync(0xFFFFFFFFu, !done);
    while (needy) {
        int l = __ffs(needy) - 1;
        needy &= needy - 1;
        float bax = __shfl_sync(0xFFFFFFFFu, ax, l);
        float bay = __shfl_sync(0xFFFFFFFFu, ay, l);
        float baz = __shfl_sync(0xFFFFFFFFu, az, l);
        float bn2 = __shfl_sync(0xFFFFFFFFu, n2q, l);
        float bb  = __shfl_sync(0xFFFFFFFFu, best, l);
        int   bcz = __shfl_sync(0xFFFFFFFFu, cz, l);

        int k = 4;
        while (true) {
            int z0 = max(bcz - k, 0);
            int z1 = min(bcz + k, G - 1);
            int j0 = S[z0 * (G * G)];
            int j1 = S[(z1 + 1) * (G * G)];
            float lb = CUDART_INF_F;
            for (int j = j0 + lane; j < j1; j += 32) {
                float4 p = P[j];
                float t = fmaf(baz, p.z, p.w);
                t = fmaf(bay, p.y, t);
                t = fmaf(bax, p.x, t);
                lb = fminf(lb, t);
            }
#pragma unroll
            for (int o = 16; o > 0; o >>= 1)
                lb = fminf(lb, __shfl_xor_sync(0xFFFFFFFFu, lb, o));
            bb = fminf(bb, lb);
            float bnd = (float)k * H;
            if ((z0 == 0 && z1 == G - 1) || bn2 + bb <= bnd * bnd) break;
            k *= 2;
        }
        if (lane == l) contrib = sqrtf(fmaxf(bn2 + bb, EPSF));
    }

    // block reduce -> one atomicAdd per block
#pragma unroll
    for (int o = 16; o > 0; o >>= 1)
        contrib += __shfl_down_sync(0xFFFFFFFFu, contrib, o);
    if (lane == 0) s_f[warp] = contrib;
    __syncthreads();
    if (tix == 0)
        atomicAdd(out, (s_f[0] + s_f[1] + s_f[2] + s_f[3]) * SCALE);
}

extern "C" void kernel_launch(void* const* d_in, const int* in_sizes, int n_in,
                              void* d_out, int out_size) {
    const float* xyz1 = (const float*)d_in[0];
    const float* xyz2 = (const float*)d_in[1];
    float* out = (float*)d_out;

    fused_kernel<<<NBLK, NTHR>>>(xyz1, xyz2, out);
}

// round 14
// speedup vs baseline: 1.0578x; 1.0578x over previous
#include <cuda_runtime.h>
#include <math_constants.h>

// Fixed shapes per reference setup_inputs
#define BATCH   8
#define NPTS    8192
#define NQ      (2 * BATCH * NPTS)     // 131072
#define EPSF    1e-12f
#define SCALE   (1.0f / 131072.0f)

// Grid parameters (cell hash: x fastest, z slowest)
#define G       32
#define NCELLS  (G * G * G)            // 32768
#define GLO     (-4.0f)
#define H       0.25f
#define INVH    4.0f
#define NCLOUD  16
#define BIGM    1e9f

#define NBLK    1024
#define NTHR    128

// Row stride NCELLS+4 keeps every row 16B-aligned for int4 access.
#define CSTRIDE (NCELLS + 4)

// Scratch (no cudaMalloc allowed). Zero-init at load. g_hist re-zeroed by
// phase D each launch; g_barc staggered-reset (see grid_barrier usage).
__device__ float4 g_pts[NCLOUD][NPTS];
__device__ int    g_hist[NCLOUD][NCELLS];
__device__ int    g_cellstart[NCLOUD][CSTRIDE];
__device__ int    g_btot[NBLK];
__device__ int    g_barc[4];

__device__ __forceinline__ int cell_coord(float v) {
    int c = (int)((v - GLO) * INVH);
    return min(max(c, 0), G - 1);
}

// Software grid barrier. Safe: __launch_bounds__(128,8) => 8 blocks/SM
// co-resident capability, 1024 <= 8*148, so all blocks are resident.
__device__ __forceinline__ void grid_barrier(int id) {
    __syncthreads();
    if (threadIdx.x == 0) {
        __threadfence();
        atomicAdd(&g_barc[id], 1);
        while (atomicAdd(&g_barc[id], 0) < NBLK) { }
    }
    __syncthreads();
}

// Dual-accumulator candidate scan (two independent fminf chains).
__device__ __forceinline__ void scan_pts(const float4* __restrict__ P,
                                         int j0, int j1,
                                         float ax, float ay, float az,
                                         float& lbA, float& lbB) {
    int j = j0;
    for (; j + 1 < j1; j += 2) {
        float4 p = P[j];
        float4 r = P[j + 1];
        float tA = fmaf(az, p.z, p.w);
        float tB = fmaf(az, r.z, r.w);
        tA = fmaf(ay, p.y, tA);
        tB = fmaf(ay, r.y, tB);
        tA = fmaf(ax, p.x, tA);
        tB = fmaf(ax, r.x, tB);
        lbA = fminf(lbA, tA);
        lbB = fminf(lbB, tB);
    }
    if (j < j1) {
        float4 p = P[j];
        float t = fmaf(az, p.z, p.w);
        t = fmaf(ay, p.y, t);
        t = fmaf(ax, p.x, t);
        lbA = fminf(lbA, t);
    }
}

// Exact margin from q-coord to the scanned box faces along one axis.
// lo/hi are the scanned cell range. Clamped domain faces -> no unscanned
// points beyond them -> infinite margin.
__device__ __forceinline__ float axis_margin(float qv, int lo, int hi) {
    float ml = (lo > 0)     ? (qv - (GLO + (float)lo * H))       : BIGM;
    float mh = (hi < G - 1) ? ((GLO + (float)(hi + 1) * H) - qv) : BIGM;
    return fminf(ml, mh);
}

__global__ void __launch_bounds__(NTHR, 8)
fused_kernel(const float* __restrict__ xyz1,
             const float* __restrict__ xyz2,
             float* __restrict__ out) {
    __shared__ int   s_i[32];
    __shared__ float s_f[4];

    const int tix  = threadIdx.x;
    const int lane = tix & 31;
    const int warp = tix >> 5;
    const int b    = blockIdx.x;
    const int lin  = b * NTHR + tix;

    // ================= A: histogram + rank (+ housekeeping) =================
    if (lin == 0) { out[0] = 0.0f; g_barc[3] = 0; }

    int   src    = lin >> 16;                 // 0 or 1
    int   within = lin & 0xFFFF;
    const float* pp = ((src == 0) ? xyz1 : xyz2) + (size_t)within * 3;
    float px = pp[0], py = pp[1], pz = pp[2];         // live until phase C
    int   pcloud = (src << 3) + (within >> 13);
    int   pcell  = (cell_coord(pz) * G + cell_coord(py)) * G + cell_coord(px);
    int   prank  = atomicAdd(&g_hist[pcloud][pcell], 1);  // rank within cell

    grid_barrier(0);

    // ================= B1: block-local sums over 512 cells =================
    const int cloud_b = b >> 6;                       // 64 blocks per cloud
    const int cbase   = ((b & 63) << 9) + (tix << 2); // 4 cells per thread
    int4 h = *(const int4*)&g_hist[cloud_b][cbase];
    int hs = h.x + h.y + h.z + h.w;

    int incl = hs;                                    // warp inclusive scan
#pragma unroll
    for (int o = 1; o < 32; o <<= 1) {
        int u = __shfl_up_sync(0xFFFFFFFFu, incl, o);
        if (lane >= o) incl += u;
    }
    if (lane == 31) s_i[warp] = incl;
    __syncthreads();
    int woff = 0;
#pragma unroll
    for (int w = 0; w < 4; w++) if (w < warp) woff += s_i[w];
    int ebase = woff + incl - hs;                     // block-exclusive base
    if (tix == 0) g_btot[b] = s_i[0] + s_i[1] + s_i[2] + s_i[3];

    grid_barrier(1);

    // ================= B2: cross-block offsets, write cellstart =====
    if (lin == 0) g_barc[0] = 0;          // all blocks passed barrier 0's spin
    {
        int nb = b & 63;
        int v = (tix < nb) ? g_btot[(cloud_b << 6) + tix] : 0;
#pragma unroll
        for (int o = 16; o > 0; o >>= 1)
            v += __shfl_down_sync(0xFFFFFFFFu, v, o);
        __syncthreads();
        if (lane == 0) s_i[warp] = v;
        __syncthreads();
        int off  = s_i[0] + s_i[1] + s_i[2] + s_i[3];
        int base = off + ebase;
        int4 cs;
        cs.x = base;
        cs.y = cs.x + h.x;
        cs.z = cs.y + h.y;
        cs.w = cs.z + h.z;
        *(int4*)&g_cellstart[cloud_b][cbase] = cs;
        if (nb == 0 && tix == 0) g_cellstart[cloud_b][NCELLS] = NPTS;
    }

    grid_barrier(2);

    // ================= C: rank-based scatter (no atomics) =================
    if (lin == 0) g_barc[1] = 0;
    {
        int slot = g_cellstart[pcloud][pcell] + prank;
        g_pts[pcloud][slot] =
            make_float4(px, py, pz, px * px + py * py + pz * pz);
    }

    grid_barrier(3);

    // ================= D: query + tail + reduce =================
    if (lin == 0) g_barc[2] = 0;
    ((int4*)g_hist)[lin] = make_int4(0, 0, 0, 0);   // ready for next launch

    // warp remap: spreads dense/sparse regions; warp stays 32 contiguous
    int wid  = lin >> 5;
    int nwid = (wid & 31) * 128 + (wid >> 5);       // bijection on [0,4096)
    int tid  = nwid * 32 + lane;

    int cloud_q = tid >> 13;
    int i       = tid & (NPTS - 1);
    int cand    = cloud_q ^ 8;

    float4 q = g_pts[cloud_q][i];
    float n2q = q.w;
    float ax = -2.0f * q.x, ay = -2.0f * q.y, az = -2.0f * q.z;
    int cx = cell_coord(q.x);
    int cy = cell_coord(q.y);
    int cz = cell_coord(q.z);

    const float4* __restrict__ P = g_pts[cand];
    const int*    __restrict__ S = g_cellstart[cand];

    // pass 1: 3x3x3, hoisted headers (18 independent LDGs)
    int x0 = max(cx - 1, 0);
    int x1 = min(cx + 1, G - 1);
    int j0a[9], j1a[9];
#pragma unroll
    for (int k = 0; k < 9; k++) {
        int dz = k / 3 - 1;
        int dy = k - (k / 3) * 3 - 1;
        int zc = cz + dz, yc = cy + dy;
        bool ok = ((unsigned)zc < G) && ((unsigned)yc < G);
        int row = (zc * G + yc) * G;
        j0a[k] = ok ? S[row + x0] : 0;
        j1a[k] = ok ? S[row + x1 + 1] : 0;
    }
    float bA = CUDART_INF_F, bB = CUDART_INF_F;
#pragma unroll
    for (int k = 0; k < 9; k++)
        scan_pts(P, j0a[k], j1a[k], ax, ay, az, bA, bB);
    float best = fminf(bA, bB);

    // Exact margin to unscanned space (avg ~1.5H, inf at clamped faces).
    float m1 = axis_margin(q.x, x0, x1);
    m1 = fminf(m1, axis_margin(q.y, max(cy - 1, 0), min(cy + 1, G - 1)));
    m1 = fminf(m1, axis_margin(q.z, max(cz - 1, 0), min(cz + 1, G - 1)));

    float d2 = n2q + best;
    float contrib = 0.0f;
    bool done = (d2 <= m1 * m1);
    if (done) contrib = sqrtf(fmaxf(d2, EPSF));

    // pass 2 (per-thread, parallel across needy lanes): r=2 shell only
    int xb0 = max(cx - 2, 0), xb1 = min(cx + 2, G - 1);
    if (!done) {
#pragma unroll 5
        for (int k = 0; k < 25; k++) {
            int dz = k / 5 - 2;
            int dy = k - (k / 5) * 5 - 2;
            int zc = cz + dz, yc = cy + dy;
            if ((unsigned)zc >= G || (unsigned)yc >= G) continue;
            int row = (zc * G + yc) * G;
            if (abs(dz) == 2 || abs(dy) == 2) {
                // boundary row of the shell: whole x extent
                scan_pts(P, S[row + xb0], S[row + xb1 + 1], ax, ay, az, bA, bB);
            } else {
                // interior row: only the new dx = +-2 cells
                int xm = cx - 2;
                if (xm >= 0) scan_pts(P, S[row + xm], S[row + xm + 1],
                                      ax, ay, az, bA, bB);
                int xp = cx + 2;
                if (xp < G)  scan_pts(P, S[row + xp], S[row + xp + 1],
                                      ax, ay, az, bA, bB);
            }
        }
        best = fminf(bA, bB);

        float m2 = axis_margin(q.x, xb0, xb1);
        m2 = fminf(m2, axis_margin(q.y, max(cy - 2, 0), min(cy + 2, G - 1)));
        m2 = fminf(m2, axis_margin(q.z, max(cz - 2, 0), min(cz + 2, G - 1)));

        d2 = n2q + best;
        done = (d2 <= m2 * m2);
        if (done) contrib = sqrtf(fmaxf(d2, EPSF));
    }

    // residual: warp-cooperative z-slab doubling (z slowest sort dim),
    // exact z-margin bound.
    unsigned needy = __ballot_sync(0xFFFFFFFFu, !done);
    while (needy) {
        int l = __ffs(needy) - 1;
        needy &= needy - 1;
        float bax = __shfl_sync(0xFFFFFFFFu, ax, l);
        float bay = __shfl_sync(0xFFFFFFFFu, ay, l);
        float baz = __shfl_sync(0xFFFFFFFFu, az, l);
        float bqz = __shfl_sync(0xFFFFFFFFu, q.z, l);
        float bn2 = __shfl_sync(0xFFFFFFFFu, n2q, l);
        float bb  = __shfl_sync(0xFFFFFFFFu, best, l);
        int   bcz = __shfl_sync(0xFFFFFFFFu, cz, l);

        int k = 4;
        while (true) {
            int z0 = max(bcz - k, 0);
            int z1 = min(bcz + k, G - 1);
            int j0 = S[z0 * (G * G)];
            int j1 = S[(z1 + 1) * (G * G)];
            float lb = CUDART_INF_F;
            for (int j = j0 + lane; j < j1; j += 32) {
                float4 p = P[j];
                float t = fmaf(baz, p.z, p.w);
                t = fmaf(bay, p.y, t);
                t = fmaf(bax, p.x, t);
                lb = fminf(lb, t);
            }
#pragma unroll
            for (int o = 16; o > 0; o >>= 1)
                lb = fminf(lb, __shfl_xor_sync(0xFFFFFFFFu, lb, o));
            bb = fminf(bb, lb);
            float mz = axis_margin(bqz, z0, z1);
            if ((z0 == 0 && z1 == G - 1) || bn2 + bb <= mz * mz) break;
            k *= 2;
        }
        if (lane == l) contrib = sqrtf(fmaxf(bn2 + bb, EPSF));
    }

    // block reduce -> one atomicAdd per block
#pragma unroll
    for (int o = 16; o > 0; o >>= 1)
        contrib += __shfl_down_sync(0xFFFFFFFFu, contrib, o);
    if (lane == 0) s_f[warp] = contrib;
    __syncthreads();
    if (tix == 0)
        atomicAdd(out, (s_f[0] + s_f[1] + s_f[2] + s_f[3]) * SCALE);
}

extern "C" void kernel_launch(void* const* d_in, const int* in_sizes, int n_in,
                              void* d_out, int out_size) {
    const float* xyz1 = (const float*)d_in[0];
    const float* xyz2 = (const float*)d_in[1];
    float* out = (float*)d_out;

    fused_kernel<<<NBLK, NTHR>>>(xyz1, xyz2, out);
}